// round 13
// baseline (speedup 1.0000x reference)
#include <cuda_runtime.h>
#include <cuda_bf16.h>
#include <cstdint>
#include <math.h>

#define N_TOT    8192
#define B_HALF   4096
#define D_DIM    256
#define NBLOCKS  64          // 8192 / 128 row/col blocks
#define NTILE    2080        // 64*65/2 upper-triangle tiles
#define GRID_MAIN 148
#define NTHREADS 256

#define KS8     272          // smem row stride bytes (17*16; 272 mod 128 = 16 -> conflict-free)
#define TILE8   (128 * KS8)  // 34816 per 128-row fp8 tile
#define SMEM_TOTAL (3 * TILE8)   // A + 2x B = 104448

#define FP8_SCALE 16.0f
#define FP8_INV   (1.0f / 256.0f)   // 1/SCALE^2

// Scratch (__device__ globals; every value read is rewritten each run)
__device__ uint8_t g_zn8[(size_t)N_TOT * D_DIM];        // e4m3(zn * sqrt(2*log2e) * 16)
__device__ float g_rowpart4[NBLOCKS][NBLOCKS][4][128];  // [mt][nt][wn][row], nt>=mt
__device__ float g_colpart2[NBLOCKS][NBLOCKS][2][128];  // [nt][mt][wm][col], mt<nt
__device__ float g_pos[N_TOT];
__device__ float g_finpart[NBLOCKS];
__device__ unsigned g_count = 0;
__device__ unsigned g_gen   = 0;

// ---------------------------------------------------------------------------
__device__ __forceinline__ uint32_t smem_u32(const void* p) {
    uint32_t a;
    asm("{ .reg .u64 t; cvta.to.shared.u64 t, %1; cvt.u32.u64 %0, t; }" : "=r"(a) : "l"(p));
    return a;
}
__device__ __forceinline__ float fexp2(float x) {
    float y; asm("ex2.approx.f32 %0, %1;" : "=f"(y) : "f"(x)); return y;
}
// pack 4 floats -> 4 e4m3 bytes (byte i = v_i)
__device__ __forceinline__ uint32_t pack_e4m3_4(float v0, float v1, float v2, float v3) {
    uint16_t lo, hi;
    asm("cvt.rn.satfinite.e4m3x2.f32 %0, %1, %2;" : "=h"(lo) : "f"(v1), "f"(v0));
    asm("cvt.rn.satfinite.e4m3x2.f32 %0, %1, %2;" : "=h"(hi) : "f"(v3), "f"(v2));
    return (uint32_t)lo | ((uint32_t)hi << 16);
}
#define CP_ASYNC16(dst, src) \
    asm volatile("cp.async.cg.shared.global [%0], [%1], 16;" :: "r"(dst), "l"(src))
#define CP_COMMIT() asm volatile("cp.async.commit_group;" ::: "memory")
#define CP_WAIT0()  asm volatile("cp.async.wait_group 0;" ::: "memory")

#define LDSM4(r, addr) \
    asm volatile("ldmatrix.sync.aligned.m8n8.x4.shared.b16 {%0,%1,%2,%3}, [%4];" \
        : "=r"((r)[0]), "=r"((r)[1]), "=r"((r)[2]), "=r"((r)[3]) : "r"(addr))

#define MMAFP8(c, a, b0, b1) \
    asm volatile("mma.sync.aligned.m16n8k32.row.col.f32.e4m3.e4m3.f32 " \
        "{%0,%1,%2,%3}, {%4,%5,%6,%7}, {%8,%9}, {%0,%1,%2,%3};" \
        : "+f"((c)[0]), "+f"((c)[1]), "+f"((c)[2]), "+f"((c)[3]) \
        : "r"((a)[0]), "r"((a)[1]), "r"((a)[2]), "r"((a)[3]), "r"(b0), "r"(b1))

// Sense-reversing grid barrier (148 CTAs, co-resident).
__device__ __forceinline__ void grid_barrier(unsigned& mygen) {
    __syncthreads();
    if (threadIdx.x == 0) {
        __threadfence();
        unsigned prev = atomicAdd(&g_count, 1u);
        if (prev == GRID_MAIN - 1) {
            g_count = 0;
            __threadfence();
            atomicAdd(&g_gen, 1u);
        } else {
            while (*(volatile unsigned*)&g_gen == mygen) { }
        }
        __threadfence();
    }
    __syncthreads();
    mygen++;
}

// ---------------------------------------------------------------------------
// Persistent kernel, 256 threads (8 warps, 2x4, 64x32 warp tiles), FP8 MMA.
// k-loop register double-buffered; logits in log2 domain scaled by 256
// (de-scaled by FP8_INV in the epilogue before ex2).
// ---------------------------------------------------------------------------
__global__ void __launch_bounds__(NTHREADS, 1) ntxent_mega(
        const float* __restrict__ zi, const float* __restrict__ zj,
        float* __restrict__ out) {
    extern __shared__ char smem[];
    __shared__ float red[32];

    const int tid = threadIdx.x, lane = tid & 31, w = tid >> 5;
    unsigned mygen = 0;

    // ===== Phase 1: normalize, scale by sqrt(2*log2e)*16, quantize e4m3 =====
    for (int row = blockIdx.x * 8 + w; row < N_TOT; row += GRID_MAIN * 8) {
        const float4* src = (row < B_HALF)
            ? (const float4*)(zi + (size_t)row * D_DIM)
            : (const float4*)(zj + (size_t)(row - B_HALF) * D_DIM);
        float4 a = src[2 * lane];         // elems 8*lane   .. +3
        float4 b = src[2 * lane + 1];     // elems 8*lane+4 .. +7
        float s = a.x * a.x + a.y * a.y + a.z * a.z + a.w * a.w
                + b.x * b.x + b.y * b.y + b.z * b.z + b.w * b.w;
        #pragma unroll
        for (int o = 16; o > 0; o >>= 1) s += __shfl_xor_sync(0xffffffffu, s, o);
        // dot of stored rows = 256 * log2(e) * sim / T
        float scale = (1.6986436f * FP8_SCALE) / fmaxf(sqrtf(s), 1e-8f);

        uint2 pk;
        pk.x = pack_e4m3_4(a.x * scale, a.y * scale, a.z * scale, a.w * scale);
        pk.y = pack_e4m3_4(b.x * scale, b.y * scale, b.z * scale, b.w * scale);
        *(uint2*)(g_zn8 + (size_t)row * D_DIM + lane * 8) = pk;
    }

    grid_barrier(mygen);

    // ================= Phase 2: upper-triangle fused GEMM =================
    {
        const int wm = w >> 2, wn = w & 3;                 // 2x4 warp grid
        const int warpM0 = wm * 64, warpN0 = wn * 32;      // 64x32 warp tile
        const int g = lane >> 2, tig = lane & 3;

        const uint32_t sbase = smem_u32(smem);
        const uint32_t sA = sbase;
        const uint32_t sBb = sbase + TILE8;

        // per-warp fragment base addresses (k byte-offset added per step)
        const uint32_t aAddr0 = sA + (warpM0 + (lane & 15)) * KS8 + ((lane >> 4) & 1) * 16;
        const uint32_t bOff0  = (warpN0 + ((lane & 16) >> 1) + (lane & 7)) * KS8
                              + ((lane >> 3) & 1) * 16;

        const int t0 = (blockIdx.x * NTILE) / GRID_MAIN;
        const int t1 = ((blockIdx.x + 1) * NTILE) / GRID_MAIN;

        int mt = 0, rem = t0;
        while (rem >= NBLOCKS - mt) { rem -= NBLOCKS - mt; mt++; }
        int nt = mt + rem;

        // prologue: A(mt) and B(nt) into buf0  (2048 16B granules per tile)
        {
            const char* gA = (const char*)(g_zn8 + (size_t)mt * 128 * D_DIM);
            const char* gB = (const char*)(g_zn8 + (size_t)nt * 128 * D_DIM);
            #pragma unroll
            for (int it = 0; it < 8; it++) {
                int flat = it * NTHREADS + tid;
                int r = flat >> 4, q = flat & 15;
                CP_ASYNC16(sA + r * KS8 + q * 16, gA + r * 256 + q * 16);
                CP_ASYNC16(sBb + r * KS8 + q * 16, gB + r * 256 + q * 16);
            }
        }
        CP_COMMIT();
        CP_WAIT0();
        __syncthreads();

        int cur_mt = mt;
        for (int t = t0; t < t1; t++) {
            const int buf = (t - t0) & 1;
            const bool have_next = (t + 1 < t1);
            int nmt = mt, nnt = nt + 1;
            if (nnt == NBLOCKS) { nmt = mt + 1; nnt = nmt; }

            if (have_next) {   // prefetch next tile's B into the other buffer
                const uint32_t sBn = sBb + (buf ^ 1) * TILE8;
                const char* gB = (const char*)(g_zn8 + (size_t)nnt * 128 * D_DIM);
                #pragma unroll
                for (int it = 0; it < 8; it++) {
                    int flat = it * NTHREADS + tid;
                    int r = flat >> 4, q = flat & 15;
                    CP_ASYNC16(sBn + r * KS8 + q * 16, gB + r * 256 + q * 16);
                }
            }
            CP_COMMIT();

            // ---- 128x128x256 fp8 tile GEMM (8 k-steps of 32), reg-pipelined ----
            const uint32_t sB = sBb + buf * TILE8;
            const uint32_t bAddr0 = sB + bOff0;

            float acc[4][4][4];
            #pragma unroll
            for (int mf = 0; mf < 4; mf++)
                #pragma unroll
                for (int nf = 0; nf < 4; nf++)
                    #pragma unroll
                    for (int e = 0; e < 4; e++) acc[mf][nf][e] = 0.f;

            uint32_t af[2][4][4], bf[2][2][4];
            #pragma unroll
            for (int mf = 0; mf < 4; mf++) LDSM4(af[0][mf], aAddr0 + mf * (16 * KS8));
            #pragma unroll
            for (int p = 0; p < 2; p++)    LDSM4(bf[0][p],  bAddr0 + p * (16 * KS8));

            #pragma unroll
            for (int kk = 0; kk < 8; kk++) {
                const int cur = kk & 1, nxt = cur ^ 1;
                if (kk < 7) {   // next step's LDSMs issue under this step's MMAs
                    const int kb = (kk + 1) * 32;
                    #pragma unroll
                    for (int mf = 0; mf < 4; mf++)
                        LDSM4(af[nxt][mf], aAddr0 + mf * (16 * KS8) + kb);
                    #pragma unroll
                    for (int p = 0; p < 2; p++)
                        LDSM4(bf[nxt][p],  bAddr0 + p * (16 * KS8) + kb);
                }
                #pragma unroll
                for (int mf = 0; mf < 4; mf++)
                    #pragma unroll
                    for (int nf = 0; nf < 4; nf++)
                        MMAFP8(acc[mf][nf], af[cur][mf], bf[cur][nf >> 1][(nf & 1) * 2],
                               bf[cur][nf >> 1][(nf & 1) * 2 + 1]);
            }

            // ---- epilogue: de-scale, ex2, per-warp sums -> global slots ----
            const bool is_diag = (mt == nt);
            const bool is_pos  = (nt == mt + 32);
            const int  m0 = mt * 128;

            float rowsum[8], colsum[8];
            #pragma unroll
            for (int s = 0; s < 8; s++) { rowsum[s] = 0.f; colsum[s] = 0.f; }

            if (is_diag | is_pos) {
                #pragma unroll
                for (int mf = 0; mf < 4; mf++)
                    #pragma unroll
                    for (int nf = 0; nf < 4; nf++)
                        #pragma unroll
                        for (int e = 0; e < 4; e++) {
                            float l = acc[mf][nf][e] * FP8_INV;
                            float ex = fexp2(l);
                            int lr = warpM0 + mf * 16 + g + (e >> 1) * 8;
                            int lc = warpN0 + nf * 8 + tig * 2 + (e & 1);
                            if (lr == lc) {
                                if (is_diag) ex = 0.f;
                                if (is_pos) {   // natural-log positive logit
                                    float ln = l * 0.69314718055994531f;
                                    g_pos[m0 + lr] = ln;
                                    g_pos[m0 + lr + B_HALF] = ln;
                                }
                            }
                            rowsum[mf * 2 + (e >> 1)] += ex;
                            colsum[nf * 2 + (e & 1)]  += ex;
                        }
            } else {
                #pragma unroll
                for (int mf = 0; mf < 4; mf++)
                    #pragma unroll
                    for (int nf = 0; nf < 4; nf++)
                        #pragma unroll
                        for (int e = 0; e < 4; e++) {
                            float ex = fexp2(acc[mf][nf][e] * FP8_INV);
                            rowsum[mf * 2 + (e >> 1)] += ex;
                            colsum[nf * 2 + (e & 1)]  += ex;
                        }
            }

            #pragma unroll
            for (int s = 0; s < 8; s++) {
                rowsum[s] += __shfl_xor_sync(0xffffffffu, rowsum[s], 1);
                rowsum[s] += __shfl_xor_sync(0xffffffffu, rowsum[s], 2);
            }
            #pragma unroll
            for (int s = 0; s < 8; s++) {
                colsum[s] += __shfl_xor_sync(0xffffffffu, colsum[s], 4);
                colsum[s] += __shfl_xor_sync(0xffffffffu, colsum[s], 8);
                colsum[s] += __shfl_xor_sync(0xffffffffu, colsum[s], 16);
            }
            if (tig == 0) {
                float* rp = &g_rowpart4[mt][nt][wn][0];
                #pragma unroll
                for (int mf = 0; mf < 4; mf++) {
                    rp[warpM0 + mf * 16 + g]     = rowsum[mf * 2 + 0];
                    rp[warpM0 + mf * 16 + g + 8] = rowsum[mf * 2 + 1];
                }
            }
            if (g == 0 && !is_diag) {
                float* cp = &g_colpart2[nt][mt][wm][0];
                #pragma unroll
                for (int nf = 0; nf < 4; nf++) {
                    cp[warpN0 + nf * 8 + tig * 2]     = colsum[nf * 2 + 0];
                    cp[warpN0 + nf * 8 + tig * 2 + 1] = colsum[nf * 2 + 1];
                }
            }

            CP_WAIT0();
            __syncthreads();   // B(next) visible; buf reusable

            if (have_next && nmt != cur_mt) {   // A reload on row change
                const char* gA = (const char*)(g_zn8 + (size_t)nmt * 128 * D_DIM);
                #pragma unroll
                for (int it = 0; it < 8; it++) {
                    int flat = it * NTHREADS + tid;
                    int r = flat >> 4, q = flat & 15;
                    CP_ASYNC16(sA + r * KS8 + q * 16, gA + r * 256 + q * 16);
                }
                CP_COMMIT();
                CP_WAIT0();
                __syncthreads();
                cur_mt = nmt;
            }
            mt = nmt; nt = nnt;
        }
    }

    grid_barrier(mygen);

    // ============ Phase 3: per-block logsumexp assembly (64 CTAs) ============
    if (blockIdx.x < NBLOCKS && tid < 128) {
        const int r = blockIdx.x;
        float tot = 0.f;
        for (int nt = r; nt < NBLOCKS; nt++) {
            const float* rp = &g_rowpart4[r][nt][0][0];
            tot += (rp[tid] + rp[128 + tid]) + (rp[256 + tid] + rp[384 + tid]);
        }
        for (int m = 0; m < r; m++) {
            const float* cp = &g_colpart2[r][m][0][0];
            tot += cp[tid] + cp[128 + tid];
        }
        float v = logf(tot) - g_pos[r * 128 + tid];
        #pragma unroll
        for (int o = 16; o > 0; o >>= 1) v += __shfl_xor_sync(0xffffffffu, v, o);
        if (lane == 0) red[w] = v;
        __syncwarp();
    }
    __syncthreads();
    if (blockIdx.x < NBLOCKS && tid == 0) {
        g_finpart[blockIdx.x] = (red[0] + red[1]) + (red[2] + red[3]);
    }

    grid_barrier(mygen);

    // ================= Phase 4: final mean (CTA 0) =================
    if (blockIdx.x == 0 && tid < 64) {
        float s = g_finpart[tid];
        #pragma unroll
        for (int o = 16; o > 0; o >>= 1) s += __shfl_xor_sync(0xffffffffu, s, o);
        if (lane == 0) red[8 + (tid >> 5)] = s;
        __syncwarp();
        if (tid == 0) out[0] = (red[8] + red[9]) * (1.0f / (float)N_TOT);
    }
}

// ---------------------------------------------------------------------------
extern "C" void kernel_launch(void* const* d_in, const int* in_sizes, int n_in,
                              void* d_out, int out_size) {
    const float* zi = (const float*)d_in[0];
    const float* zj = (const float*)d_in[1];
    float* out = (float*)d_out;

    cudaFuncSetAttribute(ntxent_mega, cudaFuncAttributeMaxDynamicSharedMemorySize,
                         SMEM_TOTAL);

    ntxent_mega<<<GRID_MAIN, NTHREADS, SMEM_TOTAL>>>(zi, zj, out);
}

// round 14
// speedup vs baseline: 1.0004x; 1.0004x over previous
#include <cuda_runtime.h>
#include <cuda_bf16.h>
#include <cstdint>
#include <math.h>

#define N_TOT    8192
#define B_HALF   4096
#define D_DIM    256
#define NBLOCKS  64          // 8192 / 128 row/col blocks
#define NTILE    2080        // 64*65/2 upper-triangle tiles
#define GRID_MAIN 148
#define NTHREADS 256

#define KS8     272          // smem row stride bytes (17*16; 272 mod 128 = 16 -> conflict-free)
#define TILE8   (128 * KS8)  // 34816 per 128-row fp8 tile
#define SMEM_TOTAL (3 * TILE8)   // A + 2x B = 104448

#define FP8_SCALE 16.0f
#define FP8_INV   (1.0f / 256.0f)   // 1/SCALE^2

// Scratch (__device__ globals; every value read is rewritten each run)
__device__ uint8_t g_zn8[(size_t)N_TOT * D_DIM];        // e4m3(zn * sqrt(2*log2e) * 16)
__device__ float g_rowpart4[NBLOCKS][NBLOCKS][4][128];  // [mt][nt][wn][row], nt>=mt
__device__ float g_colpart2[NBLOCKS][NBLOCKS][2][128];  // [nt][mt][wm][col], mt<nt
__device__ float g_pos[N_TOT];
__device__ float g_finpart[NBLOCKS];
__device__ unsigned g_count = 0;
__device__ unsigned g_gen   = 0;

// ---------------------------------------------------------------------------
__device__ __forceinline__ uint32_t smem_u32(const void* p) {
    uint32_t a;
    asm("{ .reg .u64 t; cvta.to.shared.u64 t, %1; cvt.u32.u64 %0, t; }" : "=r"(a) : "l"(p));
    return a;
}
__device__ __forceinline__ float fexp2(float x) {
    float y; asm("ex2.approx.f32 %0, %1;" : "=f"(y) : "f"(x)); return y;
}
// pack 4 floats -> 4 e4m3 bytes (byte i = v_i)
__device__ __forceinline__ uint32_t pack_e4m3_4(float v0, float v1, float v2, float v3) {
    uint16_t lo, hi;
    asm("cvt.rn.satfinite.e4m3x2.f32 %0, %1, %2;" : "=h"(lo) : "f"(v1), "f"(v0));
    asm("cvt.rn.satfinite.e4m3x2.f32 %0, %1, %2;" : "=h"(hi) : "f"(v3), "f"(v2));
    return (uint32_t)lo | ((uint32_t)hi << 16);
}
#define CP_ASYNC16(dst, src) \
    asm volatile("cp.async.cg.shared.global [%0], [%1], 16;" :: "r"(dst), "l"(src))
#define CP_COMMIT() asm volatile("cp.async.commit_group;" ::: "memory")
#define CP_WAIT0()  asm volatile("cp.async.wait_group 0;" ::: "memory")

#define LDSM4(r, addr) \
    asm volatile("ldmatrix.sync.aligned.m8n8.x4.shared.b16 {%0,%1,%2,%3}, [%4];" \
        : "=r"((r)[0]), "=r"((r)[1]), "=r"((r)[2]), "=r"((r)[3]) : "r"(addr))

#define MMAFP8(c, a, b0, b1) \
    asm volatile("mma.sync.aligned.m16n8k32.row.col.f32.e4m3.e4m3.f32 " \
        "{%0,%1,%2,%3}, {%4,%5,%6,%7}, {%8,%9}, {%0,%1,%2,%3};" \
        : "+f"((c)[0]), "+f"((c)[1]), "+f"((c)[2]), "+f"((c)[3]) \
        : "r"((a)[0]), "r"((a)[1]), "r"((a)[2]), "r"((a)[3]), "r"(b0), "r"(b1))

// Sense-reversing grid barrier (148 CTAs, co-resident).
__device__ __forceinline__ void grid_barrier(unsigned& mygen) {
    __syncthreads();
    if (threadIdx.x == 0) {
        __threadfence();
        unsigned prev = atomicAdd(&g_count, 1u);
        if (prev == GRID_MAIN - 1) {
            g_count = 0;
            __threadfence();
            atomicAdd(&g_gen, 1u);
        } else {
            while (*(volatile unsigned*)&g_gen == mygen) { }
        }
        __threadfence();
    }
    __syncthreads();
    mygen++;
}

// ---------------------------------------------------------------------------
// Persistent kernel, 256 threads (8 warps, 2x4, 64x32 warp tiles), FP8 MMA.
// k-loop register double-buffered; logits in log2 domain scaled by 256
// (de-scaled by FP8_INV in the epilogue before ex2).
// ---------------------------------------------------------------------------
__global__ void __launch_bounds__(NTHREADS, 1) ntxent_mega(
        const float* __restrict__ zi, const float* __restrict__ zj,
        float* __restrict__ out) {
    extern __shared__ char smem[];
    __shared__ float red[32];

    const int tid = threadIdx.x, lane = tid & 31, w = tid >> 5;
    unsigned mygen = 0;

    // ===== Phase 1: normalize, scale by sqrt(2*log2e)*16, quantize e4m3 =====
    for (int row = blockIdx.x * 8 + w; row < N_TOT; row += GRID_MAIN * 8) {
        const float4* src = (row < B_HALF)
            ? (const float4*)(zi + (size_t)row * D_DIM)
            : (const float4*)(zj + (size_t)(row - B_HALF) * D_DIM);
        float4 a = src[2 * lane];         // elems 8*lane   .. +3
        float4 b = src[2 * lane + 1];     // elems 8*lane+4 .. +7
        float s = a.x * a.x + a.y * a.y + a.z * a.z + a.w * a.w
                + b.x * b.x + b.y * b.y + b.z * b.z + b.w * b.w;
        #pragma unroll
        for (int o = 16; o > 0; o >>= 1) s += __shfl_xor_sync(0xffffffffu, s, o);
        // dot of stored rows = 256 * log2(e) * sim / T
        float scale = (1.6986436f * FP8_SCALE) / fmaxf(sqrtf(s), 1e-8f);

        uint2 pk;
        pk.x = pack_e4m3_4(a.x * scale, a.y * scale, a.z * scale, a.w * scale);
        pk.y = pack_e4m3_4(b.x * scale, b.y * scale, b.z * scale, b.w * scale);
        *(uint2*)(g_zn8 + (size_t)row * D_DIM + lane * 8) = pk;
    }

    grid_barrier(mygen);

    // ================= Phase 2: upper-triangle fused GEMM =================
    {
        const int wm = w >> 2, wn = w & 3;                 // 2x4 warp grid
        const int warpM0 = wm * 64, warpN0 = wn * 32;      // 64x32 warp tile
        const int g = lane >> 2, tig = lane & 3;

        const uint32_t sbase = smem_u32(smem);
        const uint32_t sA = sbase;
        const uint32_t sBb = sbase + TILE8;

        // per-warp fragment base addresses (k byte-offset added per step)
        const uint32_t aAddr0 = sA + (warpM0 + (lane & 15)) * KS8 + ((lane >> 4) & 1) * 16;
        const uint32_t bOff0  = (warpN0 + ((lane & 16) >> 1) + (lane & 7)) * KS8
                              + ((lane >> 3) & 1) * 16;

        const int t0 = (blockIdx.x * NTILE) / GRID_MAIN;
        const int t1 = ((blockIdx.x + 1) * NTILE) / GRID_MAIN;

        int mt = 0, rem = t0;
        while (rem >= NBLOCKS - mt) { rem -= NBLOCKS - mt; mt++; }
        int nt = mt + rem;

        // prologue: A(mt) and B(nt) into buf0  (2048 16B granules per tile)
        {
            const char* gA = (const char*)(g_zn8 + (size_t)mt * 128 * D_DIM);
            const char* gB = (const char*)(g_zn8 + (size_t)nt * 128 * D_DIM);
            #pragma unroll
            for (int it = 0; it < 8; it++) {
                int flat = it * NTHREADS + tid;
                int r = flat >> 4, q = flat & 15;
                CP_ASYNC16(sA + r * KS8 + q * 16, gA + r * 256 + q * 16);
                CP_ASYNC16(sBb + r * KS8 + q * 16, gB + r * 256 + q * 16);
            }
        }
        CP_COMMIT();
        CP_WAIT0();
        __syncthreads();

        int cur_mt = mt;
        for (int t = t0; t < t1; t++) {
            const int buf = (t - t0) & 1;
            const bool have_next = (t + 1 < t1);
            int nmt = mt, nnt = nt + 1;
            if (nnt == NBLOCKS) { nmt = mt + 1; nnt = nmt; }

            if (have_next) {   // prefetch next tile's B into the other buffer
                const uint32_t sBn = sBb + (buf ^ 1) * TILE8;
                const char* gB = (const char*)(g_zn8 + (size_t)nnt * 128 * D_DIM);
                #pragma unroll
                for (int it = 0; it < 8; it++) {
                    int flat = it * NTHREADS + tid;
                    int r = flat >> 4, q = flat & 15;
                    CP_ASYNC16(sBn + r * KS8 + q * 16, gB + r * 256 + q * 16);
                }
            }
            CP_COMMIT();

            // ---- 128x128x256 fp8 tile GEMM (8 k-steps of 32), reg-pipelined ----
            const uint32_t sB = sBb + buf * TILE8;
            const uint32_t bAddr0 = sB + bOff0;

            float acc[4][4][4];
            #pragma unroll
            for (int mf = 0; mf < 4; mf++)
                #pragma unroll
                for (int nf = 0; nf < 4; nf++)
                    #pragma unroll
                    for (int e = 0; e < 4; e++) acc[mf][nf][e] = 0.f;

            uint32_t af[2][4][4], bf[2][2][4];
            #pragma unroll
            for (int mf = 0; mf < 4; mf++) LDSM4(af[0][mf], aAddr0 + mf * (16 * KS8));
            #pragma unroll
            for (int p = 0; p < 2; p++)    LDSM4(bf[0][p],  bAddr0 + p * (16 * KS8));

            #pragma unroll
            for (int kk = 0; kk < 8; kk++) {
                const int cur = kk & 1, nxt = cur ^ 1;
                if (kk < 7) {   // next step's LDSMs issue under this step's MMAs
                    const int kb = (kk + 1) * 32;
                    #pragma unroll
                    for (int mf = 0; mf < 4; mf++)
                        LDSM4(af[nxt][mf], aAddr0 + mf * (16 * KS8) + kb);
                    #pragma unroll
                    for (int p = 0; p < 2; p++)
                        LDSM4(bf[nxt][p],  bAddr0 + p * (16 * KS8) + kb);
                }
                #pragma unroll
                for (int mf = 0; mf < 4; mf++)
                    #pragma unroll
                    for (int nf = 0; nf < 4; nf++)
                        MMAFP8(acc[mf][nf], af[cur][mf], bf[cur][nf >> 1][(nf & 1) * 2],
                               bf[cur][nf >> 1][(nf & 1) * 2 + 1]);
            }

            // ---- epilogue: de-scale, ex2, per-warp sums -> global slots ----
            const bool is_diag = (mt == nt);
            const bool is_pos  = (nt == mt + 32);
            const int  m0 = mt * 128;

            float rowsum[8], colsum[8];
            #pragma unroll
            for (int s = 0; s < 8; s++) { rowsum[s] = 0.f; colsum[s] = 0.f; }

            if (is_diag | is_pos) {
                #pragma unroll
                for (int mf = 0; mf < 4; mf++)
                    #pragma unroll
                    for (int nf = 0; nf < 4; nf++)
                        #pragma unroll
                        for (int e = 0; e < 4; e++) {
                            float l = acc[mf][nf][e] * FP8_INV;
                            float ex = fexp2(l);
                            int lr = warpM0 + mf * 16 + g + (e >> 1) * 8;
                            int lc = warpN0 + nf * 8 + tig * 2 + (e & 1);
                            if (lr == lc) {
                                if (is_diag) ex = 0.f;
                                if (is_pos) {   // natural-log positive logit
                                    float ln = l * 0.69314718055994531f;
                                    g_pos[m0 + lr] = ln;
                                    g_pos[m0 + lr + B_HALF] = ln;
                                }
                            }
                            rowsum[mf * 2 + (e >> 1)] += ex;
                            colsum[nf * 2 + (e & 1)]  += ex;
                        }
            } else {
                #pragma unroll
                for (int mf = 0; mf < 4; mf++)
                    #pragma unroll
                    for (int nf = 0; nf < 4; nf++)
                        #pragma unroll
                        for (int e = 0; e < 4; e++) {
                            float ex = fexp2(acc[mf][nf][e] * FP8_INV);
                            rowsum[mf * 2 + (e >> 1)] += ex;
                            colsum[nf * 2 + (e & 1)]  += ex;
                        }
            }

            #pragma unroll
            for (int s = 0; s < 8; s++) {
                rowsum[s] += __shfl_xor_sync(0xffffffffu, rowsum[s], 1);
                rowsum[s] += __shfl_xor_sync(0xffffffffu, rowsum[s], 2);
            }
            #pragma unroll
            for (int s = 0; s < 8; s++) {
                colsum[s] += __shfl_xor_sync(0xffffffffu, colsum[s], 4);
                colsum[s] += __shfl_xor_sync(0xffffffffu, colsum[s], 8);
                colsum[s] += __shfl_xor_sync(0xffffffffu, colsum[s], 16);
            }
            if (tig == 0) {
                float* rp = &g_rowpart4[mt][nt][wn][0];
                #pragma unroll
                for (int mf = 0; mf < 4; mf++) {
                    rp[warpM0 + mf * 16 + g]     = rowsum[mf * 2 + 0];
                    rp[warpM0 + mf * 16 + g + 8] = rowsum[mf * 2 + 1];
                }
            }
            if (g == 0 && !is_diag) {
                float* cp = &g_colpart2[nt][mt][wm][0];
                #pragma unroll
                for (int nf = 0; nf < 4; nf++) {
                    cp[warpN0 + nf * 8 + tig * 2]     = colsum[nf * 2 + 0];
                    cp[warpN0 + nf * 8 + tig * 2 + 1] = colsum[nf * 2 + 1];
                }
            }

            CP_WAIT0();
            __syncthreads();   // B(next) visible; buf reusable

            if (have_next && nmt != cur_mt) {   // A reload on row change
                const char* gA = (const char*)(g_zn8 + (size_t)nmt * 128 * D_DIM);
                #pragma unroll
                for (int it = 0; it < 8; it++) {
                    int flat = it * NTHREADS + tid;
                    int r = flat >> 4, q = flat & 15;
                    CP_ASYNC16(sA + r * KS8 + q * 16, gA + r * 256 + q * 16);
                }
                CP_COMMIT();
                CP_WAIT0();
                __syncthreads();
                cur_mt = nmt;
            }
            mt = nmt; nt = nnt;
        }
    }

    grid_barrier(mygen);

    // ============ Phase 3: per-block logsumexp assembly (64 CTAs) ============
    if (blockIdx.x < NBLOCKS && tid < 128) {
        const int r = blockIdx.x;
        float tot = 0.f;
        for (int nt = r; nt < NBLOCKS; nt++) {
            const float* rp = &g_rowpart4[r][nt][0][0];
            tot += (rp[tid] + rp[128 + tid]) + (rp[256 + tid] + rp[384 + tid]);
        }
        for (int m = 0; m < r; m++) {
            const float* cp = &g_colpart2[r][m][0][0];
            tot += cp[tid] + cp[128 + tid];
        }
        float v = logf(tot) - g_pos[r * 128 + tid];
        #pragma unroll
        for (int o = 16; o > 0; o >>= 1) v += __shfl_xor_sync(0xffffffffu, v, o);
        if (lane == 0) red[w] = v;
        __syncwarp();
    }
    __syncthreads();
    if (blockIdx.x < NBLOCKS && tid == 0) {
        g_finpart[blockIdx.x] = (red[0] + red[1]) + (red[2] + red[3]);
    }

    grid_barrier(mygen);

    // ================= Phase 4: final mean (CTA 0) =================
    if (blockIdx.x == 0 && tid < 64) {
        float s = g_finpart[tid];
        #pragma unroll
        for (int o = 16; o > 0; o >>= 1) s += __shfl_xor_sync(0xffffffffu, s, o);
        if (lane == 0) red[8 + (tid >> 5)] = s;
        __syncwarp();
        if (tid == 0) out[0] = (red[8] + red[9]) * (1.0f / (float)N_TOT);
    }
}

// ---------------------------------------------------------------------------
extern "C" void kernel_launch(void* const* d_in, const int* in_sizes, int n_in,
                              void* d_out, int out_size) {
    const float* zi = (const float*)d_in[0];
    const float* zj = (const float*)d_in[1];
    float* out = (float*)d_out;

    cudaFuncSetAttribute(ntxent_mega, cudaFuncAttributeMaxDynamicSharedMemorySize,
                         SMEM_TOTAL);

    ntxent_mega<<<GRID_MAIN, NTHREADS, SMEM_TOTAL>>>(zi, zj, out);
}

// round 15
// speedup vs baseline: 1.0034x; 1.0029x over previous
#include <cuda_runtime.h>
#include <cuda_bf16.h>
#include <cstdint>
#include <math.h>

#define N_TOT    8192
#define B_HALF   4096
#define D_DIM    256
#define NBLOCKS  64          // 8192 / 128 row/col blocks
#define NTILE    2080        // 64*65/2 upper-triangle tiles
#define GRID_MAIN 148
#define NTHREADS 256

#define KS8     272          // smem row stride bytes (17*16; 272 mod 128 = 16 -> conflict-free)
#define TILE8   (128 * KS8)  // 34816 per 128-row fp8 tile
#define SMEM_TOTAL (3 * TILE8)   // A + 2x B = 104448

#define FP8_SCALE 16.0f
#define FP8_INV   (1.0f / 256.0f)   // 1/SCALE^2

// Scratch (__device__ globals; every value read is rewritten each run)
__device__ uint8_t g_zn8[(size_t)N_TOT * D_DIM];        // e4m3(zn * sqrt(2*log2e) * 16)
__device__ float g_rowpart4[NBLOCKS][NBLOCKS][4][128];  // [mt][nt][wn][row], nt>=mt
__device__ float g_colpart2[NBLOCKS][NBLOCKS][2][128];  // [nt][mt][wm][col], mt<nt
__device__ float g_pos[N_TOT];
__device__ float g_finpart[NBLOCKS];
__device__ unsigned g_count = 0;
__device__ unsigned g_gen   = 0;

// ---------------------------------------------------------------------------
__device__ __forceinline__ uint32_t smem_u32(const void* p) {
    uint32_t a;
    asm("{ .reg .u64 t; cvta.to.shared.u64 t, %1; cvt.u32.u64 %0, t; }" : "=r"(a) : "l"(p));
    return a;
}
__device__ __forceinline__ float fexp2(float x) {
    float y; asm("ex2.approx.f32 %0, %1;" : "=f"(y) : "f"(x)); return y;
}
// pack 4 floats -> 4 e4m3 bytes (byte i = v_i)
__device__ __forceinline__ uint32_t pack_e4m3_4(float v0, float v1, float v2, float v3) {
    uint16_t lo, hi;
    asm("cvt.rn.satfinite.e4m3x2.f32 %0, %1, %2;" : "=h"(lo) : "f"(v1), "f"(v0));
    asm("cvt.rn.satfinite.e4m3x2.f32 %0, %1, %2;" : "=h"(hi) : "f"(v3), "f"(v2));
    return (uint32_t)lo | ((uint32_t)hi << 16);
}
#define CP_ASYNC16(dst, src) \
    asm volatile("cp.async.cg.shared.global [%0], [%1], 16;" :: "r"(dst), "l"(src))
#define CP_COMMIT() asm volatile("cp.async.commit_group;" ::: "memory")
#define CP_WAIT0()  asm volatile("cp.async.wait_group 0;" ::: "memory")

#define LDSM4(r, addr) \
    asm volatile("ldmatrix.sync.aligned.m8n8.x4.shared.b16 {%0,%1,%2,%3}, [%4];" \
        : "=r"((r)[0]), "=r"((r)[1]), "=r"((r)[2]), "=r"((r)[3]) : "r"(addr))

#define MMAFP8(c, a, b0, b1) \
    asm volatile("mma.sync.aligned.m16n8k32.row.col.f32.e4m3.e4m3.f32 " \
        "{%0,%1,%2,%3}, {%4,%5,%6,%7}, {%8,%9}, {%0,%1,%2,%3};" \
        : "+f"((c)[0]), "+f"((c)[1]), "+f"((c)[2]), "+f"((c)[3]) \
        : "r"((a)[0]), "r"((a)[1]), "r"((a)[2]), "r"((a)[3]), "r"(b0), "r"(b1))

// Sense-reversing grid barrier (148 CTAs, co-resident).
__device__ __forceinline__ void grid_barrier(unsigned& mygen) {
    __syncthreads();
    if (threadIdx.x == 0) {
        __threadfence();
        unsigned prev = atomicAdd(&g_count, 1u);
        if (prev == GRID_MAIN - 1) {
            g_count = 0;
            __threadfence();
            atomicAdd(&g_gen, 1u);
        } else {
            while (*(volatile unsigned*)&g_gen == mygen) { }
        }
        __threadfence();
    }
    __syncthreads();
    mygen++;
}

// ---------------------------------------------------------------------------
// Persistent kernel, 256 threads (8 warps, 2x4, 64x32 warp tiles), FP8 MMA.
// k-loop register double-buffered; logits in log2 domain scaled by 256
// (de-scaled by FP8_INV in the epilogue before ex2).
// ---------------------------------------------------------------------------
__global__ void __launch_bounds__(NTHREADS, 1) ntxent_mega(
        const float* __restrict__ zi, const float* __restrict__ zj,
        float* __restrict__ out) {
    extern __shared__ char smem[];
    __shared__ float red[32];

    const int tid = threadIdx.x, lane = tid & 31, w = tid >> 5;
    unsigned mygen = 0;

    // ===== Phase 1: normalize, scale by sqrt(2*log2e)*16, quantize e4m3 =====
    for (int row = blockIdx.x * 8 + w; row < N_TOT; row += GRID_MAIN * 8) {
        const float4* src = (row < B_HALF)
            ? (const float4*)(zi + (size_t)row * D_DIM)
            : (const float4*)(zj + (size_t)(row - B_HALF) * D_DIM);
        float4 a = src[2 * lane];         // elems 8*lane   .. +3
        float4 b = src[2 * lane + 1];     // elems 8*lane+4 .. +7
        float s = a.x * a.x + a.y * a.y + a.z * a.z + a.w * a.w
                + b.x * b.x + b.y * b.y + b.z * b.z + b.w * b.w;
        #pragma unroll
        for (int o = 16; o > 0; o >>= 1) s += __shfl_xor_sync(0xffffffffu, s, o);
        // dot of stored rows = 256 * log2(e) * sim / T
        float scale = (1.6986436f * FP8_SCALE) / fmaxf(sqrtf(s), 1e-8f);

        uint2 pk;
        pk.x = pack_e4m3_4(a.x * scale, a.y * scale, a.z * scale, a.w * scale);
        pk.y = pack_e4m3_4(b.x * scale, b.y * scale, b.z * scale, b.w * scale);
        *(uint2*)(g_zn8 + (size_t)row * D_DIM + lane * 8) = pk;
    }

    grid_barrier(mygen);

    // ================= Phase 2: upper-triangle fused GEMM =================
    {
        const int wm = w >> 2, wn = w & 3;                 // 2x4 warp grid
        const int warpM0 = wm * 64, warpN0 = wn * 32;      // 64x32 warp tile
        const int g = lane >> 2, tig = lane & 3;

        const uint32_t sbase = smem_u32(smem);
        const uint32_t sA = sbase;
        const uint32_t sBb = sbase + TILE8;

        // per-warp fragment base addresses (k byte-offset added per step)
        const uint32_t aAddr0 = sA + (warpM0 + (lane & 15)) * KS8 + ((lane >> 4) & 1) * 16;
        const uint32_t bOff0  = (warpN0 + ((lane & 16) >> 1) + (lane & 7)) * KS8
                              + ((lane >> 3) & 1) * 16;

        const int t0 = (blockIdx.x * NTILE) / GRID_MAIN;
        const int t1 = ((blockIdx.x + 1) * NTILE) / GRID_MAIN;

        int mt = 0, rem = t0;
        while (rem >= NBLOCKS - mt) { rem -= NBLOCKS - mt; mt++; }
        int nt = mt + rem;

        // prologue: A(mt) and B(nt) into buf0  (2048 16B granules per tile)
        {
            const char* gA = (const char*)(g_zn8 + (size_t)mt * 128 * D_DIM);
            const char* gB = (const char*)(g_zn8 + (size_t)nt * 128 * D_DIM);
            #pragma unroll
            for (int it = 0; it < 8; it++) {
                int flat = it * NTHREADS + tid;
                int r = flat >> 4, q = flat & 15;
                CP_ASYNC16(sA + r * KS8 + q * 16, gA + r * 256 + q * 16);
                CP_ASYNC16(sBb + r * KS8 + q * 16, gB + r * 256 + q * 16);
            }
        }
        CP_COMMIT();
        CP_WAIT0();
        __syncthreads();

        int cur_mt = mt;
        for (int t = t0; t < t1; t++) {
            const int buf = (t - t0) & 1;
            const bool have_next = (t + 1 < t1);
            int nmt = mt, nnt = nt + 1;
            if (nnt == NBLOCKS) { nmt = mt + 1; nnt = nmt; }

            if (have_next) {   // prefetch next tile's B into the other buffer
                const uint32_t sBn = sBb + (buf ^ 1) * TILE8;
                const char* gB = (const char*)(g_zn8 + (size_t)nnt * 128 * D_DIM);
                #pragma unroll
                for (int it = 0; it < 8; it++) {
                    int flat = it * NTHREADS + tid;
                    int r = flat >> 4, q = flat & 15;
                    CP_ASYNC16(sBn + r * KS8 + q * 16, gB + r * 256 + q * 16);
                }
            }
            CP_COMMIT();

            // ---- 128x128x256 fp8 tile GEMM (8 k-steps of 32), reg-pipelined ----
            const uint32_t sB = sBb + buf * TILE8;
            const uint32_t bAddr0 = sB + bOff0;

            float acc[4][4][4];
            #pragma unroll
            for (int mf = 0; mf < 4; mf++)
                #pragma unroll
                for (int nf = 0; nf < 4; nf++)
                    #pragma unroll
                    for (int e = 0; e < 4; e++) acc[mf][nf][e] = 0.f;

            uint32_t af[2][4][4], bf[2][2][4];
            #pragma unroll
            for (int mf = 0; mf < 4; mf++) LDSM4(af[0][mf], aAddr0 + mf * (16 * KS8));
            #pragma unroll
            for (int p = 0; p < 2; p++)    LDSM4(bf[0][p],  bAddr0 + p * (16 * KS8));

            #pragma unroll
            for (int kk = 0; kk < 8; kk++) {
                const int cur = kk & 1, nxt = cur ^ 1;
                if (kk < 7) {   // next step's LDSMs issue under this step's MMAs
                    const int kb = (kk + 1) * 32;
                    #pragma unroll
                    for (int mf = 0; mf < 4; mf++)
                        LDSM4(af[nxt][mf], aAddr0 + mf * (16 * KS8) + kb);
                    #pragma unroll
                    for (int p = 0; p < 2; p++)
                        LDSM4(bf[nxt][p],  bAddr0 + p * (16 * KS8) + kb);
                }
                #pragma unroll
                for (int mf = 0; mf < 4; mf++)
                    #pragma unroll
                    for (int nf = 0; nf < 4; nf++)
                        MMAFP8(acc[mf][nf], af[cur][mf], bf[cur][nf >> 1][(nf & 1) * 2],
                               bf[cur][nf >> 1][(nf & 1) * 2 + 1]);
            }

            // ---- epilogue: de-scale, ex2, per-warp sums -> global slots ----
            const bool is_diag = (mt == nt);
            const bool is_pos  = (nt == mt + 32);
            const int  m0 = mt * 128;

            float rowsum[8], colsum[8];
            #pragma unroll
            for (int s = 0; s < 8; s++) { rowsum[s] = 0.f; colsum[s] = 0.f; }

            if (is_diag | is_pos) {
                #pragma unroll
                for (int mf = 0; mf < 4; mf++)
                    #pragma unroll
                    for (int nf = 0; nf < 4; nf++)
                        #pragma unroll
                        for (int e = 0; e < 4; e++) {
                            float l = acc[mf][nf][e] * FP8_INV;
                            float ex = fexp2(l);
                            int lr = warpM0 + mf * 16 + g + (e >> 1) * 8;
                            int lc = warpN0 + nf * 8 + tig * 2 + (e & 1);
                            if (lr == lc) {
                                if (is_diag) ex = 0.f;
                                if (is_pos) {   // natural-log positive logit
                                    float ln = l * 0.69314718055994531f;
                                    g_pos[m0 + lr] = ln;
                                    g_pos[m0 + lr + B_HALF] = ln;
                                }
                            }
                            rowsum[mf * 2 + (e >> 1)] += ex;
                            colsum[nf * 2 + (e & 1)]  += ex;
                        }
            } else {
                #pragma unroll
                for (int mf = 0; mf < 4; mf++)
                    #pragma unroll
                    for (int nf = 0; nf < 4; nf++)
                        #pragma unroll
                        for (int e = 0; e < 4; e++) {
                            float ex = fexp2(acc[mf][nf][e] * FP8_INV);
                            rowsum[mf * 2 + (e >> 1)] += ex;
                            colsum[nf * 2 + (e & 1)]  += ex;
                        }
            }

            #pragma unroll
            for (int s = 0; s < 8; s++) {
                rowsum[s] += __shfl_xor_sync(0xffffffffu, rowsum[s], 1);
                rowsum[s] += __shfl_xor_sync(0xffffffffu, rowsum[s], 2);
            }
            #pragma unroll
            for (int s = 0; s < 8; s++) {
                colsum[s] += __shfl_xor_sync(0xffffffffu, colsum[s], 4);
                colsum[s] += __shfl_xor_sync(0xffffffffu, colsum[s], 8);
                colsum[s] += __shfl_xor_sync(0xffffffffu, colsum[s], 16);
            }
            if (tig == 0) {
                float* rp = &g_rowpart4[mt][nt][wn][0];
                #pragma unroll
                for (int mf = 0; mf < 4; mf++) {
                    rp[warpM0 + mf * 16 + g]     = rowsum[mf * 2 + 0];
                    rp[warpM0 + mf * 16 + g + 8] = rowsum[mf * 2 + 1];
                }
            }
            if (g == 0 && !is_diag) {
                float* cp = &g_colpart2[nt][mt][wm][0];
                #pragma unroll
                for (int nf = 0; nf < 4; nf++) {
                    cp[warpN0 + nf * 8 + tig * 2]     = colsum[nf * 2 + 0];
                    cp[warpN0 + nf * 8 + tig * 2 + 1] = colsum[nf * 2 + 1];
                }
            }

            CP_WAIT0();
            __syncthreads();   // B(next) visible; buf reusable

            if (have_next && nmt != cur_mt) {   // A reload on row change
                const char* gA = (const char*)(g_zn8 + (size_t)nmt * 128 * D_DIM);
                #pragma unroll
                for (int it = 0; it < 8; it++) {
                    int flat = it * NTHREADS + tid;
                    int r = flat >> 4, q = flat & 15;
                    CP_ASYNC16(sA + r * KS8 + q * 16, gA + r * 256 + q * 16);
                }
                CP_COMMIT();
                CP_WAIT0();
                __syncthreads();
                cur_mt = nmt;
            }
            mt = nmt; nt = nnt;
        }
    }

    grid_barrier(mygen);

    // ============ Phase 3: per-block logsumexp assembly (64 CTAs) ============
    if (blockIdx.x < NBLOCKS && tid < 128) {
        const int r = blockIdx.x;
        float tot = 0.f;
        for (int nt = r; nt < NBLOCKS; nt++) {
            const float* rp = &g_rowpart4[r][nt][0][0];
            tot += (rp[tid] + rp[128 + tid]) + (rp[256 + tid] + rp[384 + tid]);
        }
        for (int m = 0; m < r; m++) {
            const float* cp = &g_colpart2[r][m][0][0];
            tot += cp[tid] + cp[128 + tid];
        }
        float v = logf(tot) - g_pos[r * 128 + tid];
        #pragma unroll
        for (int o = 16; o > 0; o >>= 1) v += __shfl_xor_sync(0xffffffffu, v, o);
        if (lane == 0) red[w] = v;
        __syncwarp();
    }
    __syncthreads();
    if (blockIdx.x < NBLOCKS && tid == 0) {
        g_finpart[blockIdx.x] = (red[0] + red[1]) + (red[2] + red[3]);
    }

    grid_barrier(mygen);

    // ================= Phase 4: final mean (CTA 0) =================
    if (blockIdx.x == 0 && tid < 64) {
        float s = g_finpart[tid];
        #pragma unroll
        for (int o = 16; o > 0; o >>= 1) s += __shfl_xor_sync(0xffffffffu, s, o);
        if (lane == 0) red[8 + (tid >> 5)] = s;
        __syncwarp();
        if (tid == 0) out[0] = (red[8] + red[9]) * (1.0f / (float)N_TOT);
    }
}

// ---------------------------------------------------------------------------
extern "C" void kernel_launch(void* const* d_in, const int* in_sizes, int n_in,
                              void* d_out, int out_size) {
    const float* zi = (const float*)d_in[0];
    const float* zj = (const float*)d_in[1];
    float* out = (float*)d_out;

    cudaFuncSetAttribute(ntxent_mega, cudaFuncAttributeMaxDynamicSharedMemorySize,
                         SMEM_TOTAL);

    ntxent_mega<<<GRID_MAIN, NTHREADS, SMEM_TOTAL>>>(zi, zj, out);
}